// round 17
// baseline (speedup 1.0000x reference)
#include <cuda_runtime.h>
#include <cuda_fp16.h>
#include <math.h>
#include <stdint.h>

#define B_  64
#define T_  512
#define C_  512
#define NTC (T_ * C_)
#define TOT (B_ * T_ * C_)

// ---------------- scratch (__device__ globals; no allocation allowed) -------
__device__ float g_part1[B_ * 16 * 2];            // input stats partials
__device__ float g_part2[B_ * 16 * 2];            // Y stats partials (from trigemm)
__device__ __align__(16) __half g_yf[TOT];        // tri-mix output fp16
__device__ __align__(16) __half g_x1tf[TOT];      // LN1^T fp16
__device__ __align__(16) __half g_hf[TOT];        // gelu out fp16
__device__ __align__(16) __half g_mtf[T_ * T_];   // tril-masked Mtri fp16
__device__ __align__(16) __half g_w1f[C_ * C_], g_w2f[C_ * C_];

// ---------------- PTX helpers (sm_80-class: valid on compute_103) ----------
__device__ __forceinline__ uint32_t smem_u32(const void* p) {
    uint32_t a;
    asm("{ .reg .u64 t; cvta.to.shared.u64 t, %1; cvt.u32.u64 %0, t; }"
        : "=r"(a) : "l"(p));
    return a;
}
__device__ __forceinline__ void ldmx4(uint32_t* r, uint32_t a) {
    asm volatile("ldmatrix.sync.aligned.m8n8.x4.shared.b16 {%0,%1,%2,%3}, [%4];"
                 : "=r"(r[0]), "=r"(r[1]), "=r"(r[2]), "=r"(r[3]) : "r"(a));
}
__device__ __forceinline__ void mma_f16(float* c, const uint32_t* a, const uint32_t* b) {
    asm volatile(
        "mma.sync.aligned.m16n8k16.row.col.f32.f16.f16.f32 "
        "{%0,%1,%2,%3}, {%4,%5,%6,%7}, {%8,%9}, {%0,%1,%2,%3};"
        : "+f"(c[0]), "+f"(c[1]), "+f"(c[2]), "+f"(c[3])
        : "r"(a[0]), "r"(a[1]), "r"(a[2]), "r"(a[3]), "r"(b[0]), "r"(b[1]));
}
__device__ __forceinline__ void cp16(uint32_t sdst, const void* gsrc) {
    asm volatile("cp.async.cg.shared.global [%0], [%1], 16;"
                 :: "r"(sdst), "l"(gsrc));
}
#define CP_COMMIT() asm volatile("cp.async.commit_group;" ::: "memory")
#define CP_WAIT(n)  asm volatile("cp.async.wait_group %0;" :: "n"(n) : "memory")

__device__ __forceinline__ uint32_t h2u(__half2 h) {
    uint32_t u; memcpy(&u, &h, 4); return u;
}

// smem tile: 128 rows x 32 fp16 (64B), padded to 80B/row (conflict-free ldmatrix)
#define STRIDE   80
#define TILE_B   (128 * STRIDE)          // 10240
#define F1_STAGE (2 * TILE_B)            // 20480 (A tile + B tile)
#define SMEM_F16 (2 * F1_STAGE)          // 40960 (double buffered)

// common fragment-load + MMA inner step
#define GEMM_CORE(aB, bB)                                                     \
    _Pragma("unroll")                                                         \
    for (int ks = 0; ks < 2; ++ks) {                                          \
        int kso = ks * 32;                                                    \
        uint32_t ah[4][4], bh[4][2];                                          \
        _Pragma("unroll")                                                     \
        for (int mi = 0; mi < 4; ++mi)                                        \
            ldmx4(ah[mi], (aB) + mi * (16 * STRIDE) + kso);                   \
        _Pragma("unroll")                                                     \
        for (int jj = 0; jj < 2; ++jj) {                                      \
            uint32_t t4[4];                                                   \
            ldmx4(t4, (bB) + jj * (16 * STRIDE) + kso);                       \
            bh[2 * jj][0] = t4[0]; bh[2 * jj][1] = t4[1];                     \
            bh[2 * jj + 1][0] = t4[2]; bh[2 * jj + 1][1] = t4[3];             \
        }                                                                     \
        _Pragma("unroll")                                                     \
        for (int mi = 0; mi < 4; ++mi)                                        \
            _Pragma("unroll")                                                 \
            for (int ni = 0; ni < 4; ++ni)                                    \
                mma_f16(acc[mi][ni], ah[mi], bh[ni]);                         \
    }

#define DECL_ACC()                                                            \
    float acc[4][4][4];                                                       \
    _Pragma("unroll")                                                         \
    for (int i = 0; i < 4; i++)                                               \
        _Pragma("unroll")                                                     \
        for (int j = 0; j < 4; j++)                                           \
            _Pragma("unroll")                                                 \
            for (int e = 0; e < 4; e++) acc[i][j][e] = 0.f;

// ---------------------------------------------------------------------------
// Tri GEMM: Yh[b,m,n] = fp16( sum_{k<=diag} Mtri[m,k]*X1T[b,n,k] + trib[m]
//                             + inputs[b,m,n] );  emits per-CTA (sum, sumsq).
// ---------------------------------------------------------------------------
__global__ __launch_bounds__(256, 2)
void gemm_tri(const __half* __restrict__ AG, const __half* __restrict__ BGall,
              const float* __restrict__ bias, const float* __restrict__ ResAll,
              __half* __restrict__ OutYall, float* __restrict__ part) {
    extern __shared__ char smem[];
    const int Kd = 512;
    int tid = threadIdx.x, wid = tid >> 5, lane = tid & 31;
    int n0 = blockIdx.x * 128, m0 = blockIdx.y * 128;
    size_t bz = blockIdx.z;
    const __half* BG = BGall + bz * NTC;
    const float* Res = ResAll + bz * NTC;
    __half* OutY = OutYall + bz * NTC;

    uint32_t sb = smem_u32(smem);
    DECL_ACC()

    int nch = (m0 + 128) / 32;          // K truncated at diagonal tile

    auto load_tile = [&](const __half* G, int row0, uint32_t dst, int k0) {
#pragma unroll
        for (int it = 0; it < 2; ++it) {
            int seg = tid + it * 256;
            int r = seg >> 2, c8 = (seg & 3) * 8;
            size_t go = (size_t)(row0 + r) * Kd + k0 + c8;
            cp16(dst + (uint32_t)(r * STRIDE + c8 * 2), G + go);
        }
    };
    auto load_chunk = [&](int c, int s) {
        uint32_t base = sb + s * F1_STAGE;
        int k0 = c * 32;
        load_tile(AG, m0, base, k0);
        load_tile(BG, n0, base + TILE_B, k0);
    };

    int aRow = (wid & 1) * 64 + ((lane >> 3) & 1) * 8 + (lane & 7);
    int aCol = (lane >> 4) * 16;
    int bRow = (wid >> 1) * 32 + (lane >> 4) * 8 + (lane & 7);
    int bCol = ((lane >> 3) & 1) * 16;

    load_chunk(0, 0);
    CP_COMMIT();

    for (int c = 0; c < nch; ++c) {
        int s = c & 1;
        if (c + 1 < nch) { load_chunk(c + 1, s ^ 1); CP_COMMIT(); CP_WAIT(1); }
        else             { CP_WAIT(0); }
        __syncthreads();
        uint32_t aB = sb + s * F1_STAGE + aRow * STRIDE + aCol;
        uint32_t bB = sb + s * F1_STAGE + TILE_B + bRow * STRIDE + bCol;
        GEMM_CORE(aB, bB)
        __syncthreads();
    }

    int mwb = m0 + (wid & 1) * 64;
    int nwb = n0 + (wid >> 1) * 32;
    int mr = lane >> 2, nc = (lane & 3) * 2;
    float s = 0.f, s2 = 0.f;
#pragma unroll
    for (int mi = 0; mi < 4; ++mi)
#pragma unroll
        for (int ni = 0; ni < 4; ++ni) {
            int n = nwb + ni * 8 + nc;
#pragma unroll
            for (int half = 0; half < 2; ++half) {
                int m = mwb + mi * 16 + mr + half * 8;
                float tb = bias[m];
                float2 rv = *(const float2*)(Res + (size_t)m * 512 + n);
                float v0 = acc[mi][ni][half * 2 + 0] + tb + rv.x;
                float v1 = acc[mi][ni][half * 2 + 1] + tb + rv.y;
                s  += v0 + v1;
                s2 += v0 * v0 + v1 * v1;
                *(__half2*)(OutY + (size_t)m * 512 + n) = __floats2half2_rn(v0, v1);
            }
        }
    __syncthreads();
    float* sh  = (float*)smem;
    float* sh2 = sh + 256;
    sh[tid] = s; sh2[tid] = s2;
    __syncthreads();
    for (int o = 128; o > 0; o >>= 1) {
        if (tid < o) { sh[tid] += sh[tid + o]; sh2[tid] += sh2[tid + o]; }
        __syncthreads();
    }
    if (tid == 0) {
        int slot = (int)bz * 16 + blockIdx.y * 4 + blockIdx.x;
        part[slot * 2 + 0] = sh[0];
        part[slot * 2 + 1] = sh2[0];
    }
}

// ---------------------------------------------------------------------------
// Dense MLP GEMM with fused LN2.
// MODE 1: A = LN2(yf) computed on the fly;  OutH = fp16(gelu(acc + bias[n]))
// MODE 2: A = hf (cp.async);  OutF = acc + bias[n] + LN2(yf)[m,n]  (residual)
// Both compute mu2/rs2 inline from part2.
// ---------------------------------------------------------------------------
template <int MODE>
__global__ __launch_bounds__(256, 2)
void gemm_mlp(const __half* __restrict__ AG, const __half* __restrict__ BG,
              const float* __restrict__ bias,
              const __half* __restrict__ YF, const float* __restrict__ LW,
              const float* __restrict__ LB, const float* __restrict__ part,
              float* __restrict__ OutF, __half* __restrict__ OutH) {
    extern __shared__ char smem[];
    __shared__ float s_mu, s_rs;
    const int Kd = 512;
    int tid = threadIdx.x, wid = tid >> 5, lane = tid & 31;
    int n0 = blockIdx.x * 128, m0 = blockIdx.y * 128;
    int b = blockIdx.y >> 2;             // 4 m-blocks per batch

    if (tid == 0) {
        float s = 0.f, s2 = 0.f;
#pragma unroll
        for (int i = 0; i < 16; ++i) {
            s  += part[(b * 16 + i) * 2 + 0];
            s2 += part[(b * 16 + i) * 2 + 1];
        }
        float m = s / (float)NTC;
        s_mu = m;
        s_rs = rsqrtf(s2 / (float)NTC - m * m + 1e-5f);
    }
    __syncthreads();
    float mu = s_mu, rs = s_rs;

    uint32_t sb = smem_u32(smem);
    DECL_ACC()

    // B side: weights via cp.async
    auto load_B = [&](uint32_t dst, int k0) {
#pragma unroll
        for (int it = 0; it < 2; ++it) {
            int seg = tid + it * 256;
            int r = seg >> 2, c8 = (seg & 3) * 8;
            size_t go = (size_t)(n0 + r) * Kd + k0 + c8;
            cp16(dst + (uint32_t)(r * STRIDE + c8 * 2), BG + go);
        }
    };
    // A side MODE 2: hf via cp.async
    auto load_A_cp = [&](uint32_t dst, int k0) {
#pragma unroll
        for (int it = 0; it < 2; ++it) {
            int seg = tid + it * 256;
            int r = seg >> 2, c8 = (seg & 3) * 8;
            size_t go = (size_t)(m0 + r) * Kd + k0 + c8;
            cp16(dst + (uint32_t)(r * STRIDE + c8 * 2), AG + go);
        }
    };
    // A side MODE 1: LN2 applied on the fly (LDG + compute + STS)
    auto load_A_ln = [&](uint32_t dst, int k0) {
#pragma unroll
        for (int it = 0; it < 2; ++it) {
            int seg = tid + it * 256;
            int r = seg >> 2, c8 = (seg & 3) * 8;
            int m = m0 + r, t = m & 511;
            uint4 yv = *(const uint4*)(YF + (size_t)m * 512 + k0 + c8);
            const float* wp = LW + (size_t)t * 512 + k0 + c8;
            const float* bp = LB + (size_t)t * 512 + k0 + c8;
            float4 w0 = *(const float4*)wp;
            float4 w1 = *(const float4*)(wp + 4);
            float4 b0 = *(const float4*)bp;
            float4 b1 = *(const float4*)(bp + 4);
            float ws[8] = {w0.x, w0.y, w0.z, w0.w, w1.x, w1.y, w1.z, w1.w};
            float bs[8] = {b0.x, b0.y, b0.z, b0.w, b1.x, b1.y, b1.z, b1.w};
            const __half2* yh = (const __half2*)&yv;
            uint32_t o[4];
#pragma unroll
            for (int e = 0; e < 4; ++e) {
                float y0 = __low2float(yh[e]), y1 = __high2float(yh[e]);
                float v0 = (y0 - mu) * rs * ws[2 * e]     + bs[2 * e];
                float v1 = (y1 - mu) * rs * ws[2 * e + 1] + bs[2 * e + 1];
                o[e] = h2u(__floats2half2_rn(v0, v1));
            }
            *(uint4*)(smem + (dst - sb) + r * STRIDE + c8 * 2) =
                make_uint4(o[0], o[1], o[2], o[3]);
        }
    };
    auto load_chunk = [&](int c, int s) {
        uint32_t base = sb + s * F1_STAGE;
        int k0 = c * 32;
        if (MODE == 1) load_A_ln(base, k0);
        else           load_A_cp(base, k0);
        load_B(base + TILE_B, k0);
    };

    int aRow = (wid & 1) * 64 + ((lane >> 3) & 1) * 8 + (lane & 7);
    int aCol = (lane >> 4) * 16;
    int bRow = (wid >> 1) * 32 + (lane >> 4) * 8 + (lane & 7);
    int bCol = ((lane >> 3) & 1) * 16;

    load_chunk(0, 0);
    CP_COMMIT();

    for (int c = 0; c < 16; ++c) {
        int s = c & 1;
        if (c + 1 < 16) { load_chunk(c + 1, s ^ 1); CP_COMMIT(); CP_WAIT(1); }
        else            { CP_WAIT(0); }
        __syncthreads();
        uint32_t aB = sb + s * F1_STAGE + aRow * STRIDE + aCol;
        uint32_t bB = sb + s * F1_STAGE + TILE_B + bRow * STRIDE + bCol;
        GEMM_CORE(aB, bB)
        __syncthreads();
    }

    int mwb = m0 + (wid & 1) * 64;
    int nwb = n0 + (wid >> 1) * 32;
    int mr = lane >> 2, nc = (lane & 3) * 2;
#pragma unroll
    for (int mi = 0; mi < 4; ++mi)
#pragma unroll
        for (int ni = 0; ni < 4; ++ni) {
            int n = nwb + ni * 8 + nc;
#pragma unroll
            for (int half = 0; half < 2; ++half) {
                int m = mwb + mi * 16 + mr + half * 8;
                float v0 = acc[mi][ni][half * 2 + 0];
                float v1 = acc[mi][ni][half * 2 + 1];
                float2 bb = *(const float2*)(bias + n);
                if (MODE == 1) {
                    float t0 = v0 + bb.x, t1 = v1 + bb.y;
                    float h0 = 0.5f * t0 * (1.0f + erff(t0 * 0.70710678118654752f));
                    float h1 = 0.5f * t1 * (1.0f + erff(t1 * 0.70710678118654752f));
                    *(__half2*)(OutH + (size_t)m * 512 + n) = __floats2half2_rn(h0, h1);
                } else {
                    int t = m & 511;
                    __half2 yv = *(const __half2*)(YF + (size_t)m * 512 + n);
                    float2 wv = *(const float2*)(LW + (size_t)t * 512 + n);
                    float2 lb = *(const float2*)(LB + (size_t)t * 512 + n);
                    v0 += bb.x + (__low2float(yv)  - mu) * rs * wv.x + lb.x;
                    v1 += bb.y + (__high2float(yv) - mu) * rs * wv.y + lb.y;
                    *(float2*)(OutF + (size_t)m * 512 + n) = make_float2(v0, v1);
                }
            }
        }
}

// ---------------------------------------------------------------------------
// Weight prep: z=0 Mtri -> tril-masked fp16; z=1 w1 -> fp16; z=2 w2 -> fp16
// ---------------------------------------------------------------------------
__global__ void split_w(const float* __restrict__ Mt, const float* __restrict__ w1,
                        const float* __restrict__ w2) {
    int idx = blockIdx.x * 256 + threadIdx.x;
    int z = blockIdx.y;
    if (z == 0) {
        int i = idx >> 9, j = idx & 511;
        float v = (j <= i) ? Mt[idx] : 0.f;
        g_mtf[idx] = __float2half(v);
    } else if (z == 1) {
        g_w1f[idx] = __float2half(w1[idx]);
    } else {
        g_w2f[idx] = __float2half(w2[idx]);
    }
}

// ---------------------------------------------------------------------------
// Per-batch stats of fp32 input, split 16 ways (deterministic two-pass).
// ---------------------------------------------------------------------------
__global__ void stats_part(const float* __restrict__ x, float* __restrict__ part) {
    int b = blockIdx.y, slice = blockIdx.x;
    const float4* p = (const float4*)(x + (size_t)b * NTC) + (size_t)slice * 4096;
    float s = 0.f, s2 = 0.f;
    for (int i = threadIdx.x; i < 4096; i += 256) {
        float4 v = p[i];
        s  += v.x + v.y + v.z + v.w;
        s2 += v.x * v.x + v.y * v.y + v.z * v.z + v.w * v.w;
    }
    __shared__ float sh[256], sh2[256];
    sh[threadIdx.x] = s; sh2[threadIdx.x] = s2;
    __syncthreads();
    for (int o = 128; o > 0; o >>= 1) {
        if (threadIdx.x < o) {
            sh[threadIdx.x] += sh[threadIdx.x + o];
            sh2[threadIdx.x] += sh2[threadIdx.x + o];
        }
        __syncthreads();
    }
    if (threadIdx.x == 0) {
        part[(b * 16 + slice) * 2 + 0] = sh[0];
        part[(b * 16 + slice) * 2 + 1] = sh2[0];
    }
}

// ---------------------------------------------------------------------------
// LN1 + transpose -> fp16 (stats finalized inline from part1)
// ---------------------------------------------------------------------------
__global__ void ln1t(const float* __restrict__ x, const float* __restrict__ w,
                     const float* __restrict__ bias, const float* __restrict__ part,
                     __half* __restrict__ xtf) {
    __shared__ float tile[32][33];
    __shared__ float s_mu, s_rs;
    int b = blockIdx.z;
    int t0 = blockIdx.x * 32, c0 = blockIdx.y * 32;
    int tx = threadIdx.x, ty = threadIdx.y;
    int tid = ty * 32 + tx;
    if (tid == 0) {
        float s = 0.f, s2 = 0.f;
#pragma unroll
        for (int i = 0; i < 16; ++i) {
            s  += part[(b * 16 + i) * 2 + 0];
            s2 += part[(b * 16 + i) * 2 + 1];
        }
        float mm = s / (float)NTC;
        s_mu = mm;
        s_rs = rsqrtf(s2 / (float)NTC - mm * mm + 1e-5f);
    }
    __syncthreads();
    float m = s_mu, r = s_rs;
#pragma unroll
    for (int k = 0; k < 4; ++k) {
        int t = t0 + ty + k * 8, c = c0 + tx;
        size_t idx = (size_t)t * C_ + c;
        tile[ty + k * 8][tx] = (x[(size_t)b * NTC + idx] - m) * r * w[idx] + bias[idx];
    }
    __syncthreads();
#pragma unroll
    for (int k = 0; k < 4; ++k) {
        int c = c0 + ty + k * 8, t = t0 + tx;
        xtf[(size_t)b * NTC + (size_t)c * T_ + t] = __float2half(tile[tx][ty + k * 8]);
    }
}

// ---------------------------------------------------------------------------
extern "C" void kernel_launch(void* const* d_in, const int* in_sizes, int n_in,
                              void* d_out, int out_size) {
    const float* inputs = (const float*)d_in[0];
    const float* ln1w   = (const float*)d_in[1];
    const float* ln1b   = (const float*)d_in[2];
    const float* ln2w   = (const float*)d_in[3];
    const float* ln2b   = (const float*)d_in[4];
    const float* triM   = (const float*)d_in[5];
    const float* trib   = (const float*)d_in[6];
    const float* d1w    = (const float*)d_in[7];
    const float* d1b    = (const float*)d_in[8];
    const float* d2w    = (const float*)d_in[9];
    const float* d2b    = (const float*)d_in[10];
    float* out = (float*)d_out;

    float *part1, *part2;
    __half *yf, *x1tf, *hf, *mtf, *w1f, *w2f;
    cudaGetSymbolAddress((void**)&part1, g_part1);
    cudaGetSymbolAddress((void**)&part2, g_part2);
    cudaGetSymbolAddress((void**)&yf,   g_yf);
    cudaGetSymbolAddress((void**)&x1tf, g_x1tf);
    cudaGetSymbolAddress((void**)&hf,   g_hf);
    cudaGetSymbolAddress((void**)&mtf,  g_mtf);
    cudaGetSymbolAddress((void**)&w1f,  g_w1f);
    cudaGetSymbolAddress((void**)&w2f,  g_w2f);

    cudaFuncSetAttribute(gemm_tri,
                         cudaFuncAttributeMaxDynamicSharedMemorySize, SMEM_F16);
    cudaFuncSetAttribute(gemm_mlp<1>,
                         cudaFuncAttributeMaxDynamicSharedMemorySize, SMEM_F16);
    cudaFuncSetAttribute(gemm_mlp<2>,
                         cudaFuncAttributeMaxDynamicSharedMemorySize, SMEM_F16);

    // 0) weight prep (tril-masked Mtri, d1_w, d2_w -> fp16)
    split_w<<<dim3(1024, 3), 256>>>(triM, d1w, d2w);

    // 1) partial stats of inputs
    stats_part<<<dim3(16, B_), 256>>>(inputs, part1);

    // 2) X1T = fp16(transpose(LN1(inputs)))   (stats finalized inline)
    ln1t<<<dim3(T_ / 32, C_ / 32, B_), dim3(32, 8)>>>(inputs, ln1w, ln1b, part1,
                                                       x1tf);

    // 3) Yh = fp16(tril(M) @ X1 + tri_b + inputs), fused per-tile Y stats
    gemm_tri<<<dim3(4, 4, B_), 256, SMEM_F16>>>(mtf, x1tf, trib, inputs, yf, part2);

    // 4) H = fp16(gelu(LN2(Y) @ d1_w^T + d1_b))   (LN2 fused into A producer)
    gemm_mlp<1><<<dim3(4, 256), 256, SMEM_F16>>>(nullptr, w1f, d1b,
                                                 yf, ln2w, ln2b, part2,
                                                 nullptr, hf);

    // 5) out = LN2(Y) + H @ d2_w^T + d2_b          (LN2 residual in epilogue)
    gemm_mlp<2><<<dim3(4, 256), 256, SMEM_F16>>>(hf, w2f, d2b,
                                                 yf, ln2w, ln2b, part2,
                                                 out, nullptr);
}